// round 3
// baseline (speedup 1.0000x reference)
#include <cuda_runtime.h>
#include <cuda_bf16.h>
#include <cstdint>

// ---------------------------------------------------------------------------
// Scratch in __device__ globals (no allocations allowed).
// g_Bf: W1 bf16 fragments packed per mma.m16n8k16 B-lane:
//   for (n, ks, q): uint4 {bh0, bh1, bl0, bl1} at bf16 index n*1024 + ks*32 + q*8
//   where within a k16 step: k = half*8 + q*2 + parity, comp = half (hi) / 2+half (lo)
// ---------------------------------------------------------------------------
static __device__ __align__(16) __nv_bfloat16 g_Bf[56 * 1024];
static __device__ __align__(16) float g_W2[112];  // [56][2], rows >= 50 zero
static __device__ __align__(8)  float g_b1[56];   // zero-padded
static __device__ __align__(8)  float g_b2[2];

// ---------------- kernel 1: materialize W1/W2/biases from MPO cores ----------
__global__ void build_weights(const float* __restrict__ A1, const float* __restrict__ A2,
                              const float* __restrict__ A3, const float* __restrict__ A4,
                              const float* __restrict__ A5, const float* __restrict__ b1,
                              const float* __restrict__ B1, const float* __restrict__ B2,
                              const float* __restrict__ B3, const float* __restrict__ b2) {
    __shared__ float sL[500];    // [i][j][p2][v]
    __shared__ float sR1[200];   // [p3][l][m][x]
    __shared__ float sRt[5000];  // [p2][k][w][l][m][x]
    const int t = threadIdx.x;

    for (int e = t; e < 200; e += 256) {
        int x = e & 1, m = (e >> 1) & 1, l = (e >> 2) % 5, p3 = e / 20;
        float s = 0.f;
        for (int p4 = 0; p4 < 10; ++p4)
            s += A4[((p3 * 5 + l) * 10 + p4) * 2 + x] * A5[p4 * 2 + m];
        sR1[e] = s;
    }
    for (int e = t; e < 500; e += 256) {
        int v = e % 5, p2 = (e / 5) % 10, j = (e / 50) % 5, i = e / 250;
        float s = 0.f;
        for (int p1 = 0; p1 < 10; ++p1)
            s += A1[i * 10 + p1] * A2[((p1 * 5 + j) * 10 + p2) * 5 + v];
        sL[e] = s;
    }
    __syncthreads();
    for (int e = t; e < 5000; e += 256) {
        int x = e & 1, m = (e >> 1) & 1, l = (e >> 2) % 5;
        int w = (e / 20) % 5, k = (e / 100) % 5, p2 = e / 500;
        float s = 0.f;
        for (int p3 = 0; p3 < 10; ++p3)
            s += A3[((p2 * 5 + k) * 10 + p3) * 5 + w] * sR1[((p3 * 5 + l) * 2 + m) * 2 + x];
        sRt[e] = s;
    }
    __syncthreads();

    // each of 16 CTAs fills 32 k-rows x 56 n-cols of the padded 512x56 W1
    const int kbeg = blockIdx.x * 32;
    for (int e = t; e < 32 * 56; e += 256) {
        const int n = e % 56;
        const int k = kbeg + e / 56;
        float val = 0.f;
        if (k < 500 && n < 50) {
            int m = k & 1, l = (k >> 1) % 5, kk = (k / 10) % 5, j = (k / 50) % 5, i = k / 250;
            int x = n & 1, w = (n >> 1) % 5, v = n / 10;
            for (int p2 = 0; p2 < 10; ++p2)
                val += sL[((i * 5 + j) * 10 + p2) * 5 + v] *
                       sRt[((((p2 * 5 + kk) * 5 + w) * 5 + l) * 2 + m) * 2 + x];
        }
        __nv_bfloat16 hi = __float2bfloat16(val);
        __nv_bfloat16 lo = __float2bfloat16(val - __bfloat162float(hi));
        const int ks = k >> 4, kk16 = k & 15;
        const int half = kk16 >> 3, q = (kk16 >> 1) & 3, parity = kk16 & 1;
        const int base = n * 1024 + ks * 32 + q * 8;
        g_Bf[base + half * 2 + parity] = hi;       // comps 0,1
        g_Bf[base + 4 + half * 2 + parity] = lo;   // comps 2,3
    }

    if (blockIdx.x == 0) {
        for (int e = t; e < 56; e += 256) g_b1[e] = (e < 50) ? b1[e] : 0.f;
        if (t < 2) g_b2[t] = b2[t];
        for (int e = t; e < 112; e += 256) {
            const int v = e & 1, r = e >> 1;
            float s = 0.f;
            if (r < 50) {
                int i = r / 25, j = (r / 5) % 5, kq = r % 5;
                for (int p1 = 0; p1 < 10; ++p1)
                    for (int p2 = 0; p2 < 10; ++p2)
                        s += B1[i * 10 + p1] * B2[((p1 * 5 + j) * 10 + p2) * 2 + v] *
                             B3[p2 * 5 + kq];
            }
            g_W2[e] = s;
        }
    }
}

// ---------------- main kernel helpers ----------------
__device__ __forceinline__ void split2(float vx, float vy, uint32_t& h, uint32_t& l) {
    __nv_bfloat162 hb = __floats2bfloat162_rn(vx, vy);
    float rx = vx - __bfloat162float(hb.x);
    float ry = vy - __bfloat162float(hb.y);
    __nv_bfloat162 lb = __floats2bfloat162_rn(rx, ry);
    h = (uint32_t)__bfloat16_as_ushort(hb.x) | ((uint32_t)__bfloat16_as_ushort(hb.y) << 16);
    l = (uint32_t)__bfloat16_as_ushort(lb.x) | ((uint32_t)__bfloat16_as_ushort(lb.y) << 16);
}

__device__ __forceinline__ void mma16816(float* d, uint32_t a0, uint32_t a1,
                                         uint32_t a2, uint32_t a3,
                                         uint32_t b0, uint32_t b1) {
    asm volatile(
        "mma.sync.aligned.m16n8k16.row.col.f32.bf16.bf16.f32 "
        "{%0,%1,%2,%3}, {%4,%5,%6,%7}, {%8,%9}, {%0,%1,%2,%3};"
        : "+f"(d[0]), "+f"(d[1]), "+f"(d[2]), "+f"(d[3])
        : "r"(a0), "r"(a1), "r"(a2), "r"(a3), "r"(b0), "r"(b1));
}

// one k16 step: 7 n-tiles x 3 split-terms
__device__ __forceinline__ void do_k16(float (&acc)[7][4], const __nv_bfloat16* bp,
                                       uint32_t ah0, uint32_t ah1, uint32_t ah2, uint32_t ah3,
                                       uint32_t al0, uint32_t al1, uint32_t al2, uint32_t al3) {
    #pragma unroll
    for (int t = 0; t < 7; ++t) {
        const uint4 bv = *reinterpret_cast<const uint4*>(bp + t * 8192);
        mma16816(acc[t], ah0, ah1, ah2, ah3, bv.x, bv.y);  // hi*hi
        mma16816(acc[t], ah0, ah1, ah2, ah3, bv.z, bv.w);  // hi*lo
        mma16816(acc[t], al0, al1, al2, al3, bv.x, bv.y);  // lo*hi
    }
}

// ---------------- kernel 2: fused forward ----------------
// 256 threads = 8 warps; warp owns 16 rows x 56 cols. No smem, no barriers.
__global__ void __launch_bounds__(256)
tn_forward(const float* __restrict__ x, float* __restrict__ out) {
    const int tid = threadIdx.x;
    const int warp = tid >> 5;
    const int lane = tid & 31;
    const int q = lane & 3;          // quad index
    const int kq = q * 2;            // k/n pair offset within fragment
    const int nrow = lane >> 2;      // 0..7

    const int r = (blockIdx.x << 7) + (warp << 4) + nrow;  // rows r and r+8
    const float* px0 = x + (size_t)r * 500;
    const float* px1 = px0 + 4000;   // row r+8

    const __nv_bfloat16* bp = g_Bf + (nrow * 1024 + q * 8);

    float acc[7][4];
    #pragma unroll
    for (int t = 0; t < 7; ++t)
        acc[t][0] = acc[t][1] = acc[t][2] = acc[t][3] = 0.f;

    #pragma unroll 4
    for (int ks = 0; ks < 31; ++ks) {
        const int k = ks * 16 + kq;
        const float2 u00 = *reinterpret_cast<const float2*>(px0 + k);
        const float2 u02 = *reinterpret_cast<const float2*>(px0 + k + 8);
        const float2 u10 = *reinterpret_cast<const float2*>(px1 + k);
        const float2 u12 = *reinterpret_cast<const float2*>(px1 + k + 8);
        uint32_t ah0, ah1, ah2, ah3, al0, al1, al2, al3;
        split2(u00.x, u00.y, ah0, al0);
        split2(u10.x, u10.y, ah1, al1);
        split2(u02.x, u02.y, ah2, al2);
        split2(u12.x, u12.y, ah3, al3);
        do_k16(acc, bp + ks * 32, ah0, ah1, ah2, ah3, al0, al1, al2, al3);
    }
    {   // tail: ks=31 covers k 496..511; only 496..499 are real
        const int k = 496 + kq;
        float2 u00 = make_float2(0.f, 0.f), u10 = make_float2(0.f, 0.f);
        if (kq < 4) {
            u00 = *reinterpret_cast<const float2*>(px0 + k);
            u10 = *reinterpret_cast<const float2*>(px1 + k);
        }
        uint32_t ah0, ah1, al0, al1;
        split2(u00.x, u00.y, ah0, al0);
        split2(u10.x, u10.y, ah1, al1);
        do_k16(acc, bp + 31 * 32, ah0, ah1, 0u, 0u, al0, al1, 0u, 0u);
    }

    // epilogue: bias + relu + layer2 (56 -> 2), quad reduce, store
    float s00 = 0.f, s01 = 0.f, s10 = 0.f, s11 = 0.f;
    #pragma unroll
    for (int t = 0; t < 7; ++t) {
        const int n0 = t * 8 + kq;
        const float2 bv = *reinterpret_cast<const float2*>(g_b1 + n0);
        const float4 wv = *reinterpret_cast<const float4*>(g_W2 + 2 * n0);
        float h;
        h = fmaxf(acc[t][0] + bv.x, 0.f); s00 = fmaf(h, wv.x, s00); s01 = fmaf(h, wv.y, s01);
        h = fmaxf(acc[t][1] + bv.y, 0.f); s00 = fmaf(h, wv.z, s00); s01 = fmaf(h, wv.w, s01);
        h = fmaxf(acc[t][2] + bv.x, 0.f); s10 = fmaf(h, wv.x, s10); s11 = fmaf(h, wv.y, s11);
        h = fmaxf(acc[t][3] + bv.y, 0.f); s10 = fmaf(h, wv.z, s10); s11 = fmaf(h, wv.w, s11);
    }
    #pragma unroll
    for (int d = 1; d <= 2; d <<= 1) {
        s00 += __shfl_xor_sync(0xffffffffu, s00, d);
        s01 += __shfl_xor_sync(0xffffffffu, s01, d);
        s10 += __shfl_xor_sync(0xffffffffu, s10, d);
        s11 += __shfl_xor_sync(0xffffffffu, s11, d);
    }
    if (q == 0) {
        const float b20 = g_b2[0], b21 = g_b2[1];
        *reinterpret_cast<float2*>(out + 2 * (size_t)r) = make_float2(s00 + b20, s01 + b21);
        *reinterpret_cast<float2*>(out + 2 * (size_t)(r + 8)) = make_float2(s10 + b20, s11 + b21);
    }
}

extern "C" void kernel_launch(void* const* d_in, const int* in_sizes, int n_in,
                              void* d_out, int out_size) {
    const float* x = (const float*)d_in[0];
    build_weights<<<16, 256>>>(
        (const float*)d_in[1], (const float*)d_in[2], (const float*)d_in[3],
        (const float*)d_in[4], (const float*)d_in[5], (const float*)d_in[6],
        (const float*)d_in[7], (const float*)d_in[8], (const float*)d_in[9],
        (const float*)d_in[10]);
    tn_forward<<<512, 256>>>(x, (float*)d_out);
}

// round 5
// speedup vs baseline: 1.4543x; 1.4543x over previous
#include <cuda_runtime.h>
#include <cuda_bf16.h>
#include <cstdint>

// ---------------------------------------------------------------------------
// Scratch (__device__ globals; no allocations allowed).
// g_Bf: W1 bf16 fragments, COALESCED layout: uint4 per (ks, t, lane):
//   ((ks*7 + t)*32 + lane) * 8 bf16, lane = nrow*4 + q
//   within the 8 bf16: [half*2+parity]=hi, [4+half*2+parity]=lo,
//   where k = ks*16 + half*8 + q*2 + parity, n = t*8 + nrow.
// ---------------------------------------------------------------------------
static __device__ __align__(16) __nv_bfloat16 g_Bf[32 * 7 * 32 * 8];  // 114688 B
static __device__ __align__(16) float g_W2[112];  // [56][2], rows >= 50 zero
static __device__ __align__(8)  float g_b1[56];   // zero-padded
static __device__ __align__(8)  float g_b2[2];

// ---------------- kernel 1: materialize W1/W2/biases from MPO cores ----------
__global__ void build_weights(const float* __restrict__ A1, const float* __restrict__ A2,
                              const float* __restrict__ A3, const float* __restrict__ A4,
                              const float* __restrict__ A5, const float* __restrict__ b1,
                              const float* __restrict__ B1, const float* __restrict__ B2,
                              const float* __restrict__ B3, const float* __restrict__ b2) {
    __shared__ float sL[500];    // [i][j][p2][v]
    __shared__ float sR1[200];   // [p3][l][m][x]
    __shared__ float sRt[5000];  // [p2][k][w][l][m][x]
    const int t = threadIdx.x;

    for (int e = t; e < 200; e += 256) {
        int x = e & 1, m = (e >> 1) & 1, l = (e >> 2) % 5, p3 = e / 20;
        float s = 0.f;
        for (int p4 = 0; p4 < 10; ++p4)
            s += A4[((p3 * 5 + l) * 10 + p4) * 2 + x] * A5[p4 * 2 + m];
        sR1[e] = s;
    }
    for (int e = t; e < 500; e += 256) {
        int v = e % 5, p2 = (e / 5) % 10, j = (e / 50) % 5, i = e / 250;
        float s = 0.f;
        for (int p1 = 0; p1 < 10; ++p1)
            s += A1[i * 10 + p1] * A2[((p1 * 5 + j) * 10 + p2) * 5 + v];
        sL[e] = s;
    }
    __syncthreads();
    for (int e = t; e < 5000; e += 256) {
        int x = e & 1, m = (e >> 1) & 1, l = (e >> 2) % 5;
        int w = (e / 20) % 5, k = (e / 100) % 5, p2 = e / 500;
        float s = 0.f;
        for (int p3 = 0; p3 < 10; ++p3)
            s += A3[((p2 * 5 + k) * 10 + p3) * 5 + w] * sR1[((p3 * 5 + l) * 2 + m) * 2 + x];
        sRt[e] = s;
    }
    __syncthreads();

    const int kbeg = blockIdx.x * 32;   // 16 CTAs cover k 0..511
    for (int e = t; e < 32 * 56; e += 256) {
        const int n = e % 56;
        const int k = kbeg + e / 56;
        float val = 0.f;
        if (k < 500 && n < 50) {
            int m = k & 1, l = (k >> 1) % 5, kk = (k / 10) % 5, j = (k / 50) % 5, i = k / 250;
            int x = n & 1, w = (n >> 1) % 5, v = n / 10;
            for (int p2 = 0; p2 < 10; ++p2)
                val += sL[((i * 5 + j) * 10 + p2) * 5 + v] *
                       sRt[((((p2 * 5 + kk) * 5 + w) * 5 + l) * 2 + m) * 2 + x];
        }
        __nv_bfloat16 hi = __float2bfloat16(val);
        __nv_bfloat16 lo = __float2bfloat16(val - __bfloat162float(hi));
        const int tt = n >> 3, nr = n & 7;
        const int ks = k >> 4, kk16 = k & 15;
        const int half = kk16 >> 3, q = (kk16 >> 1) & 3, par = kk16 & 1;
        const int base = ((ks * 7 + tt) * 32 + (nr * 4 + q)) * 8;
        g_Bf[base + half * 2 + par] = hi;
        g_Bf[base + 4 + half * 2 + par] = lo;
    }

    if (blockIdx.x == 0) {
        for (int e = t; e < 56; e += 256) g_b1[e] = (e < 50) ? b1[e] : 0.f;
        if (t < 2) g_b2[t] = b2[t];
        for (int e = t; e < 112; e += 256) {
            const int v = e & 1, r = e >> 1;
            float s = 0.f;
            if (r < 50) {
                int i = r / 25, j = (r / 5) % 5, kq = r % 5;
                for (int p1 = 0; p1 < 10; ++p1)
                    for (int p2 = 0; p2 < 10; ++p2)
                        s += B1[i * 10 + p1] * B2[((p1 * 5 + j) * 10 + p2) * 2 + v] *
                             B3[p2 * 5 + kq];
            }
            g_W2[e] = s;
        }
    }
}

// ---------------- main kernel helpers ----------------
__device__ __forceinline__ uint32_t smem_u32(const void* p) {
    uint32_t a;
    asm("{ .reg .u64 t; cvta.to.shared.u64 t, %1; cvt.u32.u64 %0, t; }" : "=r"(a) : "l"(p));
    return a;
}
__device__ __forceinline__ void cp16(uint32_t dst, const float* src) {
    asm volatile("cp.async.cg.shared.global [%0], [%1], 16;" :: "r"(dst), "l"(src) : "memory");
}
__device__ __forceinline__ void cp16z(uint32_t dst, const float* src) {
    asm volatile("cp.async.cg.shared.global [%0], [%1], 16, 0;" :: "r"(dst), "l"(src) : "memory");
}
__device__ __forceinline__ void split2(float vx, float vy, uint32_t& h, uint32_t& l) {
    __nv_bfloat162 hb = __floats2bfloat162_rn(vx, vy);
    float rx = vx - __bfloat162float(hb.x);
    float ry = vy - __bfloat162float(hb.y);
    __nv_bfloat162 lb = __floats2bfloat162_rn(rx, ry);
    h = (uint32_t)__bfloat16_as_ushort(hb.x) | ((uint32_t)__bfloat16_as_ushort(hb.y) << 16);
    l = (uint32_t)__bfloat16_as_ushort(lb.x) | ((uint32_t)__bfloat16_as_ushort(lb.y) << 16);
}
__device__ __forceinline__ void mma16816(float* d, uint32_t a0, uint32_t a1,
                                         uint32_t a2, uint32_t a3,
                                         uint32_t b0, uint32_t b1) {
    asm volatile(
        "mma.sync.aligned.m16n8k16.row.col.f32.bf16.bf16.f32 "
        "{%0,%1,%2,%3}, {%4,%5,%6,%7}, {%8,%9}, {%0,%1,%2,%3};"
        : "+f"(d[0]), "+f"(d[1]), "+f"(d[2]), "+f"(d[3])
        : "r"(a0), "r"(a1), "r"(a2), "r"(a3), "r"(b0), "r"(b1));
}

// x staging: 4-stage ring, 1 kstep (16 floats) per row per stage.
// ROW_F = 20 floats (80 B): 16B-aligned cp.async dsts AND conflict-free LDS
// (20*nrow + 2q mod 32 covers all 32 banks exactly once per warp).
static constexpr int ROW_F = 20;
static constexpr int STAGE_F = 256 * ROW_F;            // floats per stage
static constexpr int STAGE_B = STAGE_F * 4;            // 20480 B
static constexpr int SMEM_TOTAL = 4 * STAGE_B;         // 81920 B

__device__ __forceinline__ void load_chunk(uint32_t sbase_b, const float* xb,
                                           int ks, int rbase, int c4) {
    const int kb = ks * 16 + c4 * 4;
    const bool ok = (kb + 4 <= 500);
    #pragma unroll
    for (int i = 0; i < 4; ++i) {
        const int row = rbase + 64 * i;
        const uint32_t dst = sbase_b + (uint32_t)(row * ROW_F + c4 * 4) * 4u;
        if (ok) cp16(dst, xb + (size_t)row * 500 + kb);
        else    cp16z(dst, xb);
    }
}

// ---------------- kernel 2: fused forward ----------------
// 256 threads = 8 warps; warp owns 32 rows (2 m16 blocks) x 56 cols.
__global__ void __launch_bounds__(256, 2)
tn_forward(const float* __restrict__ x, float* __restrict__ out) {
    extern __shared__ float sx[];
    const uint32_t sbase = smem_u32(sx);
    const int tid = threadIdx.x;
    const int warp = tid >> 5, lane = tid & 31;
    const int q = lane & 3, nrow = lane >> 2;
    const int c4 = tid & 3, rbase = tid >> 2;   // cp.async mapping

    const size_t row0 = (size_t)blockIdx.x * 256;
    const float* xb = x + row0 * 500;

    // prefetch 4 stages
    #pragma unroll
    for (int s = 0; s < 4; ++s) {
        load_chunk(sbase + s * STAGE_B, xb, s, rbase, c4);
        asm volatile("cp.async.commit_group;" ::: "memory");
    }

    float acc[2][7][4];
    #pragma unroll
    for (int rb = 0; rb < 2; ++rb)
        #pragma unroll
        for (int t = 0; t < 7; ++t)
            acc[rb][t][0] = acc[rb][t][1] = acc[rb][t][2] = acc[rb][t][3] = 0.f;

    const uint4* Bp = reinterpret_cast<const uint4*>(g_Bf);

    for (int ks = 0; ks < 32; ++ks) {
        asm volatile("cp.async.wait_group 3;" ::: "memory");
        __syncthreads();
        const float* st = sx + (ks & 3) * STAGE_F;

        uint4 bf[7];
        #pragma unroll
        for (int t = 0; t < 7; ++t)
            bf[t] = __ldg(&Bp[(ks * 7 + t) * 32 + lane]);

        #pragma unroll
        for (int rb = 0; rb < 2; ++rb) {
            const int rl = warp * 32 + rb * 16 + nrow;
            const float2 u00 = *reinterpret_cast<const float2*>(st + rl * ROW_F + 2 * q);
            const float2 u10 = *reinterpret_cast<const float2*>(st + (rl + 8) * ROW_F + 2 * q);
            const float2 u02 = *reinterpret_cast<const float2*>(st + rl * ROW_F + 8 + 2 * q);
            const float2 u12 = *reinterpret_cast<const float2*>(st + (rl + 8) * ROW_F + 8 + 2 * q);
            uint32_t ah0, ah1, ah2, ah3, al0, al1, al2, al3;
            split2(u00.x, u00.y, ah0, al0);
            split2(u10.x, u10.y, ah1, al1);
            split2(u02.x, u02.y, ah2, al2);
            split2(u12.x, u12.y, ah3, al3);
            #pragma unroll
            for (int t = 0; t < 7; ++t) {
                mma16816(acc[rb][t], ah0, ah1, ah2, ah3, bf[t].x, bf[t].y);  // hi*hi
                mma16816(acc[rb][t], ah0, ah1, ah2, ah3, bf[t].z, bf[t].w);  // hi*lo
                mma16816(acc[rb][t], al0, al1, al2, al3, bf[t].x, bf[t].y);  // lo*hi
            }
        }
        __syncthreads();
        if (ks + 4 < 32)
            load_chunk(sbase + (ks & 3) * STAGE_B, xb, ks + 4, rbase, c4);
        asm volatile("cp.async.commit_group;" ::: "memory");
    }

    // epilogue: bias + relu + layer2 (56 -> 2), quad reduce, store
    const float b20 = g_b2[0], b21 = g_b2[1];
    const int kq = q * 2;
    #pragma unroll
    for (int rb = 0; rb < 2; ++rb) {
        float s00 = 0.f, s01 = 0.f, s10 = 0.f, s11 = 0.f;
        #pragma unroll
        for (int t = 0; t < 7; ++t) {
            const int n0 = t * 8 + kq;
            const float2 bv = *reinterpret_cast<const float2*>(g_b1 + n0);
            const float4 wv = *reinterpret_cast<const float4*>(g_W2 + 2 * n0);
            float h;
            h = fmaxf(acc[rb][t][0] + bv.x, 0.f); s00 = fmaf(h, wv.x, s00); s01 = fmaf(h, wv.y, s01);
            h = fmaxf(acc[rb][t][1] + bv.y, 0.f); s00 = fmaf(h, wv.z, s00); s01 = fmaf(h, wv.w, s01);
            h = fmaxf(acc[rb][t][2] + bv.x, 0.f); s10 = fmaf(h, wv.x, s10); s11 = fmaf(h, wv.y, s11);
            h = fmaxf(acc[rb][t][3] + bv.y, 0.f); s10 = fmaf(h, wv.z, s10); s11 = fmaf(h, wv.w, s11);
        }
        #pragma unroll
        for (int d = 1; d <= 2; d <<= 1) {
            s00 += __shfl_xor_sync(0xffffffffu, s00, d);
            s01 += __shfl_xor_sync(0xffffffffu, s01, d);
            s10 += __shfl_xor_sync(0xffffffffu, s10, d);
            s11 += __shfl_xor_sync(0xffffffffu, s11, d);
        }
        if (q == 0) {
            const size_t r = row0 + warp * 32 + rb * 16 + nrow;
            *reinterpret_cast<float2*>(out + 2 * r) = make_float2(s00 + b20, s01 + b21);
            *reinterpret_cast<float2*>(out + 2 * (r + 8)) = make_float2(s10 + b20, s11 + b21);
        }
    }
}

extern "C" void kernel_launch(void* const* d_in, const int* in_sizes, int n_in,
                              void* d_out, int out_size) {
    const float* x = (const float*)d_in[0];
    build_weights<<<16, 256>>>(
        (const float*)d_in[1], (const float*)d_in[2], (const float*)d_in[3],
        (const float*)d_in[4], (const float*)d_in[5], (const float*)d_in[6],
        (const float*)d_in[7], (const float*)d_in[8], (const float*)d_in[9],
        (const float*)d_in[10]);
    cudaFuncSetAttribute(tn_forward, cudaFuncAttributeMaxDynamicSharedMemorySize, SMEM_TOTAL);
    tn_forward<<<256, 256, SMEM_TOTAL>>>(x, (float*)d_out);
}